// round 7
// baseline (speedup 1.0000x reference)
#include <cuda_runtime.h>
#include <cuda_bf16.h>
#include <math.h>
#include <float.h>
#include <stdint.h>

// Problem constants
#define NPTS   131072          // 32 * 64 * 64 points
#define DDIM   64
#define KCODES 1024
#define HWSZ   4096
#define QOFF   ((size_t)NPTS)
#define QSZ    ((size_t)32*64*4096)
#define POFF   (QOFF + QSZ)

#define TAU    0.05f           // MMA top-2 gap below which we rescan exactly

#define PITCH   144            // bytes per smem row -> conflict-free ldmatrix
#define ASPLIT  (128 * PITCH)
#define BSPLIT  (128 * PITCH)
#define BBUF    (3 * BSPLIT)
// smem layout
#define SM_ESQ   0             // 1024 f32 = 4096
#define SM_FIDX  4096          // 128 int final index
#define SM_CNT   4608          // flagged counter
#define SM_LST   4624          // 128 int flagged rows
#define SM_XV    5152          // 8 warps x 64 f32 rescan x-buffers (2048 B)
#define SM_A     7200          // 3 * ASPLIT = 55296
#define SM_B     (SM_A + 3 * ASPLIT)        // 62496
#define SM_TOTAL (SM_B + 2 * BBUF)          // 173088 B

// ---- scratch (no cudaMalloc) ----
__device__ int           g_counts[KCODES];
__device__ float         g_esq[KCODES];
__device__ __nv_bfloat16 g_e0[KCODES * DDIM];
__device__ __nv_bfloat16 g_e1[KCODES * DDIM];
__device__ __nv_bfloat16 g_e2[KCODES * DDIM];

// ---- PTX helpers (baseline ISA, sm_80-compatible) ----
__device__ __forceinline__ uint32_t smem_u32(const void* p) {
    uint32_t a;
    asm("{ .reg .u64 t; cvta.to.shared.u64 t, %1; cvt.u32.u64 %0, t; }"
        : "=r"(a) : "l"(p));
    return a;
}
#define CP_ASYNC16(dst, src) \
    asm volatile("cp.async.cg.shared.global [%0], [%1], 16;" \
                 :: "r"(dst), "l"(src) : "memory")
#define CP_COMMIT() asm volatile("cp.async.commit_group;" ::: "memory")
#define CP_WAIT1()  asm volatile("cp.async.wait_group 1;" ::: "memory")
#define CP_WAIT0()  asm volatile("cp.async.wait_group 0;" ::: "memory")

#define LDSM_X4(r, addr)                                                      \
    asm volatile("ldmatrix.sync.aligned.m8n8.x4.shared.b16 {%0,%1,%2,%3}, [%4];" \
                 : "=r"((r)[0]), "=r"((r)[1]), "=r"((r)[2]), "=r"((r)[3])     \
                 : "r"(addr))

#define MMA16816(c, a, b)                                                     \
    asm volatile("mma.sync.aligned.m16n8k16.row.col.f32.bf16.bf16.f32 "       \
                 "{%0,%1,%2,%3}, {%4,%5,%6,%7}, {%8,%9}, {%0,%1,%2,%3};"      \
                 : "+f"((c)[0]), "+f"((c)[1]), "+f"((c)[2]), "+f"((c)[3])     \
                 : "r"((a)[0]), "r"((a)[1]), "r"((a)[2]), "r"((a)[3]),        \
                   "r"((b)[0]), "r"((b)[1]))

// best + second-best distance (index only for best)
__device__ __forceinline__ void upd2(float& bd, int& bi, float& sd,
                                     float d, int idx) {
    if (d < bd)      { sd = bd; bd = d; bi = idx; }
    else if (d < sd) { sd = d; }
}
__device__ __forceinline__ void merge2(float& bd, int& bi, float& sd,
                                       float obd, int obi, float osd) {
    if (obd < bd || (obd == bd && obi < bi)) {
        sd = fminf(bd, osd); bd = obd; bi = obi;
    } else {
        sd = fminf(sd, obd);
    }
}

// ---------------------------------------------------------------------------
// Prep: VERBATIM copy of the Round-1 esq kernel (empirically matches the
// reference's argmin decisions) — do not touch.
// ---------------------------------------------------------------------------
__global__ void vq_prep(const float* __restrict__ emb) {
    int k = blockIdx.x * blockDim.x + threadIdx.x;
    if (k < KCODES) {
        const float4* row = (const float4*)(emb + (size_t)k * DDIM);
        float s = 0.f;
#pragma unroll
        for (int i = 0; i < DDIM / 4; i++) {
            float4 v = row[i];
            s += v.x * v.x + v.y * v.y + v.z * v.z + v.w * v.w;
        }
        g_esq[k]    = s;
        g_counts[k] = 0;
    }
}

// Separate kernel: 3-way bf16 splits of the embedding.
__global__ void vq_split(const float* __restrict__ emb) {
    int k = blockIdx.x * blockDim.x + threadIdx.x;   // 0..1023
    const float* row = emb + (size_t)k * DDIM;
#pragma unroll 4
    for (int d = 0; d < DDIM; d++) {
        float v = row[d];
        __nv_bfloat16 h0 = __float2bfloat16_rn(v);
        float r1 = v - __bfloat162float(h0);
        __nv_bfloat16 h1 = __float2bfloat16_rn(r1);
        float r2 = r1 - __bfloat162float(h1);
        __nv_bfloat16 h2 = __float2bfloat16_rn(r2);
        g_e0[(size_t)k * DDIM + d] = h0;
        g_e1[(size_t)k * DDIM + d] = h1;
        g_e2[(size_t)k * DDIM + d] = h2;
    }
}

// ---------------------------------------------------------------------------
// Main: 256 threads (8 warps), 128 points/CTA, 1024 CTAs. mma.sync bf16x3
// for ranking; exact R1-arithmetic rescan for near-tie points.
// ---------------------------------------------------------------------------
__global__ __launch_bounds__(256, 1)
void vq_main(const float* __restrict__ in, const float* __restrict__ emb,
             float* __restrict__ out) {
    extern __shared__ char smem[];
    float* esq_s = (float*)(smem + SM_ESQ);
    int*   fidx  = (int*)(smem + SM_FIDX);
    int*   pcnt  = (int*)(smem + SM_CNT);
    int*   lst   = (int*)(smem + SM_LST);
    const uint32_t sbase = smem_u32(smem);
    const int t    = threadIdx.x;
    const int lane = t & 31;
    const int w    = t >> 5;
    const int m0   = w * 16;
    const int base = blockIdx.x * 128;
    const int b    = base >> 12;
    const int tg   = lane & 3;

    // ---- B tile prefetch via cp.async ----
    auto issue_B = [&](int tt, int buf) {
#pragma unroll
        for (int i = 0; i < 12; i++) {
            int c   = t + i * 256;
            int s   = c >> 10;
            int r   = c & 1023;
            int row = r >> 3, ch = r & 7;
            uint32_t dst = sbase + SM_B + buf * BBUF + s * BSPLIT +
                           row * PITCH + ch * 16;
            const __nv_bfloat16* srcp = (s == 0) ? g_e0 : (s == 1) ? g_e1 : g_e2;
            const char* src = (const char*)srcp +
                              ((size_t)(tt * 128 + row) * DDIM + ch * 8) * 2;
            CP_ASYNC16(dst, src);
        }
        CP_COMMIT();
    };

    issue_B(0, 0);
    issue_B(1, 1);

    if (t == 0) *pcnt = 0;
#pragma unroll
    for (int i = 0; i < KCODES / 256; i++)
        esq_s[t + i * 256] = g_esq[t + i * 256];

    // ---- A build: point t, split(-2x) into 3 bf16 rows ----
    if (t < 128) {
        const float* xp = in + (size_t)b * DDIM * HWSZ + ((base + t) & (HWSZ - 1));
        uint32_t* r0 = (uint32_t*)(smem + SM_A + 0 * ASPLIT + t * PITCH);
        uint32_t* r1 = (uint32_t*)(smem + SM_A + 1 * ASPLIT + t * PITCH);
        uint32_t* r2 = (uint32_t*)(smem + SM_A + 2 * ASPLIT + t * PITCH);
#pragma unroll
        for (int d = 0; d < DDIM; d += 2) {
            float va = -2.0f * xp[(size_t)d * HWSZ];
            float vb = -2.0f * xp[(size_t)(d + 1) * HWSZ];
            __nv_bfloat16 a0 = __float2bfloat16_rn(va);
            float ra = va - __bfloat162float(a0);
            __nv_bfloat16 a1 = __float2bfloat16_rn(ra);
            __nv_bfloat16 a2 = __float2bfloat16_rn(ra - __bfloat162float(a1));
            __nv_bfloat16 b0 = __float2bfloat16_rn(vb);
            float rb = vb - __bfloat162float(b0);
            __nv_bfloat16 b1 = __float2bfloat16_rn(rb);
            __nv_bfloat16 b2 = __float2bfloat16_rn(rb - __bfloat162float(b1));
            r0[d >> 1] = (uint32_t)__bfloat16_as_ushort(a0) |
                         ((uint32_t)__bfloat16_as_ushort(b0) << 16);
            r1[d >> 1] = (uint32_t)__bfloat16_as_ushort(a1) |
                         ((uint32_t)__bfloat16_as_ushort(b1) << 16);
            r2[d >> 1] = (uint32_t)__bfloat16_as_ushort(a2) |
                         ((uint32_t)__bfloat16_as_ushort(b2) << 16);
        }
    }
    __syncthreads();

    // ---- A fragments resident in registers ----
    uint32_t af[3][4][4];
#pragma unroll
    for (int s = 0; s < 3; s++)
#pragma unroll
        for (int k = 0; k < 4; k++) {
            uint32_t addr = sbase + SM_A + s * ASPLIT +
                            (m0 + (lane & 15)) * PITCH + k * 32 + (lane >> 4) * 16;
            LDSM_X4(af[s][k], addr);
        }

    float bd0 = FLT_MAX, sd0 = FLT_MAX, bd1 = FLT_MAX, sd1 = FLT_MAX;
    int   bi0 = 0, bi1 = 0;

    for (int tt = 0; tt < 8; tt++) {
        if (tt < 7) { CP_WAIT1(); } else { CP_WAIT0(); }
        __syncthreads();
        const uint32_t bbase = sbase + SM_B + (tt & 1) * BBUF;

#pragma unroll 2
        for (int j = 0; j < 16; j++) {
            uint32_t bf[3][2][4];
#pragma unroll
            for (int s = 0; s < 3; s++)
#pragma unroll
                for (int kk = 0; kk < 2; kk++) {
                    uint32_t addr = bbase + s * BSPLIT +
                                    (j * 8 + (lane & 7)) * PITCH +
                                    kk * 64 + (lane >> 3) * 16;
                    LDSM_X4(bf[s][kk], addr);
                }

            float accA[4] = {0.f, 0.f, 0.f, 0.f};
            float accB[4] = {0.f, 0.f, 0.f, 0.f};
#pragma unroll
            for (int k = 0; k < 4; k++) {
                const uint32_t* b0k = &bf[0][k >> 1][(k & 1) * 2];
                const uint32_t* b1k = &bf[1][k >> 1][(k & 1) * 2];
                const uint32_t* b2k = &bf[2][k >> 1][(k & 1) * 2];
                MMA16816(accA, af[0][k], b0k);   // x0*e0
                MMA16816(accB, af[0][k], b1k);   // x0*e1
                MMA16816(accB, af[1][k], b0k);   // x1*e0
                MMA16816(accA, af[1][k], b1k);   // x1*e1
                MMA16816(accB, af[0][k], b2k);   // x0*e2
                MMA16816(accA, af[2][k], b0k);   // x2*e0
            }

            const int cb = tt * 128 + j * 8 + 2 * tg;
            const float e0 = esq_s[cb], e1 = esq_s[cb + 1];
            upd2(bd0, bi0, sd0, e0 + (accA[0] + accB[0]), cb);
            upd2(bd0, bi0, sd0, e1 + (accA[1] + accB[1]), cb + 1);
            upd2(bd1, bi1, sd1, e0 + (accA[2] + accB[2]), cb);
            upd2(bd1, bi1, sd1, e1 + (accA[3] + accB[3]), cb + 1);
        }

        __syncthreads();
        if (tt + 2 < 8) issue_B(tt + 2, tt & 1);
    }

    // ---- merge top-2 across the 4 lanes sharing each row ----
#pragma unroll
    for (int off = 1; off <= 2; off <<= 1) {
        float obd = __shfl_xor_sync(0xffffffffu, bd0, off);
        int   obi = __shfl_xor_sync(0xffffffffu, bi0, off);
        float osd = __shfl_xor_sync(0xffffffffu, sd0, off);
        merge2(bd0, bi0, sd0, obd, obi, osd);
        obd = __shfl_xor_sync(0xffffffffu, bd1, off);
        obi = __shfl_xor_sync(0xffffffffu, bi1, off);
        osd = __shfl_xor_sync(0xffffffffu, sd1, off);
        merge2(bd1, bi1, sd1, obd, obi, osd);
    }
    if (tg == 0) {
        int g  = lane >> 2;
        int r0 = m0 + g, r1 = m0 + g + 8;
        fidx[r0] = bi0;
        fidx[r1] = bi1;
        if (sd0 - bd0 <= TAU) lst[atomicAdd(pcnt, 1)] = r0;
        if (sd1 - bd1 <= TAU) lst[atomicAdd(pcnt, 1)] = r1;
    }
    __syncthreads();

    // ---- near-tie rescan: one warp per flagged point, all 1024 codes,
    //      EXACT replica of Round-1 arithmetic (even/odd fma chains,
    //      dot = lo + hi, dist = esq - 2*dot, ascending strict <) ----
    {
        const int cnt = *pcnt;
        float* xv = (float*)(smem + SM_XV) + w * 64;
        for (int f = w; f < cnt; f += 8) {
            int r = lst[f];
            const float* xp = in + (size_t)b * DDIM * HWSZ +
                              ((base + r) & (HWSZ - 1));
            xv[lane]      = xp[(size_t)lane * HWSZ];
            xv[lane + 32] = xp[(size_t)(lane + 32) * HWSZ];
            __syncwarp();
            float bd = FLT_MAX; int bi = 0;
            for (int kc = 0; kc < 32; kc++) {
                int k = kc * 32 + lane;          // ascending in k per lane
                const float* ep = emb + (size_t)k * DDIM;
                float lo = 0.f, hi = 0.f;
#pragma unroll
                for (int d = 0; d < DDIM / 2; d++) {
                    lo = __fmaf_rn(xv[2 * d],     __ldg(&ep[2 * d]),     lo);
                    hi = __fmaf_rn(xv[2 * d + 1], __ldg(&ep[2 * d + 1]), hi);
                }
                float dot  = lo + hi;
                float dist = esq_s[k] - 2.0f * dot;
                if (dist < bd) { bd = dist; bi = k; }
            }
#pragma unroll
            for (int off = 16; off > 0; off >>= 1) {
                float od = __shfl_xor_sync(0xffffffffu, bd, off);
                int   oi = __shfl_xor_sync(0xffffffffu, bi, off);
                if (od < bd || (od == bd && oi < bi)) { bd = od; bi = oi; }
            }
            if (lane == 0) fidx[r] = bi;
            __syncwarp();
        }
    }
    __syncthreads();

    // ---- outputs ----
    if (t < 128) {
        int bidx = fidx[t];
        out[base + t] = (float)bidx;
        atomicAdd(&g_counts[bidx], 1);
    }
    {   // quantized scatter: 2 threads per point, 32 channels each
        int p    = t & 127;
        int half = t >> 7;
        int bidx = fidx[p];
        const float* er = emb + (size_t)bidx * DDIM + half * 32;
        float* oq = out + QOFF + (size_t)b * DDIM * HWSZ +
                    ((base + p) & (HWSZ - 1)) + (size_t)half * 32 * HWSZ;
#pragma unroll
        for (int i = 0; i < 32; i++)
            oq[(size_t)i * HWSZ] = __ldg(&er[i]);
    }
}

// ---------------------------------------------------------------------------
// Perplexity
// ---------------------------------------------------------------------------
__global__ void vq_perp(float* __restrict__ out) {
    __shared__ float red[32];
    int k = threadIdx.x;
    float p = (float)g_counts[k] * (1.0f / (float)NPTS);
    float v = p * logf(p + 1e-10f);
#pragma unroll
    for (int s = 16; s > 0; s >>= 1) v += __shfl_xor_sync(0xffffffffu, v, s);
    if ((k & 31) == 0) red[k >> 5] = v;
    __syncthreads();
    if (k < 32) {
        float wv = red[k];
#pragma unroll
        for (int s = 16; s > 0; s >>= 1) wv += __shfl_xor_sync(0xffffffffu, wv, s);
        if (k == 0) out[POFF] = expf(-wv);
    }
}

// ---------------------------------------------------------------------------
extern "C" void kernel_launch(void* const* d_in, const int* in_sizes, int n_in,
                              void* d_out, int out_size) {
    const float* x   = (const float*)d_in[0];   // (32, 64, 64, 64) fp32
    const float* emb = (const float*)d_in[1];   // (1024, 64) fp32
    float* out = (float*)d_out;

    cudaFuncSetAttribute(vq_main, cudaFuncAttributeMaxDynamicSharedMemorySize,
                         SM_TOTAL);

    vq_prep<<<8, 128>>>(emb);
    vq_split<<<8, 128>>>(emb);
    vq_main<<<NPTS / 128, 256, SM_TOTAL>>>(x, emb, out);
    vq_perp<<<1, KCODES>>>(out);
}

// round 8
// speedup vs baseline: 2.5977x; 2.5977x over previous
#include <cuda_runtime.h>
#include <cuda_bf16.h>
#include <math.h>
#include <float.h>
#include <stdint.h>

// Problem constants
#define NPTS   131072          // 32 * 64 * 64 points
#define DDIM   64
#define KCODES 1024
#define HWSZ   4096
#define QOFF   ((size_t)NPTS)
#define QSZ    ((size_t)32*64*4096)
#define POFF   (QOFF + QSZ)

#define TAU    2e-3f           // MMA top-2 gap below which we rescan exactly

#define PITCH   144            // bytes per smem row -> conflict-free ldmatrix
#define ASPLIT  (128 * PITCH)
#define BSPLIT  (128 * PITCH)
#define BBUF    (2 * BSPLIT)   // 2 splits (e0, e1) per buffer
// smem layout
#define SM_ESQ   0             // 1024 f32 = 4096
#define SM_FIDX  4096          // 128 int final index
#define SM_CNT   4608          // flagged counter
#define SM_LST   4624          // 128 int flagged rows
#define SM_XV    5152          // 8 warps x 64 f32 rescan x-buffers (2048 B)
#define SM_A     7200          // 2 * ASPLIT = 36864
#define SM_B     (SM_A + 2 * ASPLIT)        // 44064
#define SM_TOTAL (SM_B + 2 * BBUF)          // 117792 B

// ---- scratch (no cudaMalloc) ----
__device__ int           g_counts[KCODES];
__device__ float         g_esq[KCODES];
__device__ __nv_bfloat16 g_e0[KCODES * DDIM];
__device__ __nv_bfloat16 g_e1[KCODES * DDIM];

// ---- PTX helpers (baseline ISA, sm_80-compatible) ----
__device__ __forceinline__ uint32_t smem_u32(const void* p) {
    uint32_t a;
    asm("{ .reg .u64 t; cvta.to.shared.u64 t, %1; cvt.u32.u64 %0, t; }"
        : "=r"(a) : "l"(p));
    return a;
}
#define CP_ASYNC16(dst, src) \
    asm volatile("cp.async.cg.shared.global [%0], [%1], 16;" \
                 :: "r"(dst), "l"(src) : "memory")
#define CP_COMMIT() asm volatile("cp.async.commit_group;" ::: "memory")
#define CP_WAIT1()  asm volatile("cp.async.wait_group 1;" ::: "memory")
#define CP_WAIT0()  asm volatile("cp.async.wait_group 0;" ::: "memory")

#define LDSM_X4(r, addr)                                                      \
    asm volatile("ldmatrix.sync.aligned.m8n8.x4.shared.b16 {%0,%1,%2,%3}, [%4];" \
                 : "=r"((r)[0]), "=r"((r)[1]), "=r"((r)[2]), "=r"((r)[3])     \
                 : "r"(addr))

#define MMA16816(c, a, b)                                                     \
    asm volatile("mma.sync.aligned.m16n8k16.row.col.f32.bf16.bf16.f32 "       \
                 "{%0,%1,%2,%3}, {%4,%5,%6,%7}, {%8,%9}, {%0,%1,%2,%3};"      \
                 : "+f"((c)[0]), "+f"((c)[1]), "+f"((c)[2]), "+f"((c)[3])     \
                 : "r"((a)[0]), "r"((a)[1]), "r"((a)[2]), "r"((a)[3]),        \
                   "r"((b)[0]), "r"((b)[1]))

// best + second-best distance (index only for best)
__device__ __forceinline__ void upd2(float& bd, int& bi, float& sd,
                                     float d, int idx) {
    if (d < bd)      { sd = bd; bd = d; bi = idx; }
    else if (d < sd) { sd = d; }
}
__device__ __forceinline__ void merge2(float& bd, int& bi, float& sd,
                                       float obd, int obi, float osd) {
    if (obd < bd || (obd == bd && obi < bi)) {
        sd = fminf(bd, osd); bd = obd; bi = obi;
    } else {
        sd = fminf(sd, obd);
    }
}

// ---------------------------------------------------------------------------
// Prep: VERBATIM copy of the Round-1 esq kernel (matches reference decisions)
// ---------------------------------------------------------------------------
__global__ void vq_prep(const float* __restrict__ emb) {
    int k = blockIdx.x * blockDim.x + threadIdx.x;
    if (k < KCODES) {
        const float4* row = (const float4*)(emb + (size_t)k * DDIM);
        float s = 0.f;
#pragma unroll
        for (int i = 0; i < DDIM / 4; i++) {
            float4 v = row[i];
            s += v.x * v.x + v.y * v.y + v.z * v.z + v.w * v.w;
        }
        g_esq[k]    = s;
        g_counts[k] = 0;
    }
}

// 2-way bf16 splits of the embedding (e0 + e1 ≈ e to ~2^-18 rel).
__global__ void vq_split(const float* __restrict__ emb) {
    int k = blockIdx.x * blockDim.x + threadIdx.x;   // 0..1023
    const float* row = emb + (size_t)k * DDIM;
#pragma unroll 4
    for (int d = 0; d < DDIM; d++) {
        float v = row[d];
        __nv_bfloat16 h0 = __float2bfloat16_rn(v);
        float r1 = v - __bfloat162float(h0);
        __nv_bfloat16 h1 = __float2bfloat16_rn(r1);
        g_e0[(size_t)k * DDIM + d] = h0;
        g_e1[(size_t)k * DDIM + d] = h1;
    }
}

// ---------------------------------------------------------------------------
// Main: 256 threads (8 warps), 128 points/CTA, 1024 CTAs.
// 3-product bf16 mma.sync ranking + gap-gated exact R1-arithmetic rescan.
// ---------------------------------------------------------------------------
__global__ __launch_bounds__(256, 1)
void vq_main(const float* __restrict__ in, const float* __restrict__ emb,
             float* __restrict__ out) {
    extern __shared__ char smem[];
    float* esq_s = (float*)(smem + SM_ESQ);
    int*   fidx  = (int*)(smem + SM_FIDX);
    int*   pcnt  = (int*)(smem + SM_CNT);
    int*   lst   = (int*)(smem + SM_LST);
    const uint32_t sbase = smem_u32(smem);
    const int t    = threadIdx.x;
    const int lane = t & 31;
    const int w    = t >> 5;
    const int m0   = w * 16;
    const int base = blockIdx.x * 128;
    const int b    = base >> 12;
    const int tg   = lane & 3;

    // ---- B tile prefetch via cp.async: 2 splits x 128 codes x 128B ----
    auto issue_B = [&](int tt, int buf) {
#pragma unroll
        for (int i = 0; i < 8; i++) {
            int c   = t + i * 256;           // 0..2047 chunk id
            int s   = c >> 10;               // split 0/1
            int r   = c & 1023;
            int row = r >> 3, ch = r & 7;
            uint32_t dst = sbase + SM_B + buf * BBUF + s * BSPLIT +
                           row * PITCH + ch * 16;
            const __nv_bfloat16* srcp = (s == 0) ? g_e0 : g_e1;
            const char* src = (const char*)srcp +
                              ((size_t)(tt * 128 + row) * DDIM + ch * 8) * 2;
            CP_ASYNC16(dst, src);
        }
        CP_COMMIT();
    };

    issue_B(0, 0);
    issue_B(1, 1);

    if (t == 0) *pcnt = 0;
#pragma unroll
    for (int i = 0; i < KCODES / 256; i++)
        esq_s[t + i * 256] = g_esq[t + i * 256];

    // ---- A build: point t, split(-2x) into 2 bf16 rows ----
    if (t < 128) {
        const float* xp = in + (size_t)b * DDIM * HWSZ + ((base + t) & (HWSZ - 1));
        uint32_t* r0 = (uint32_t*)(smem + SM_A + 0 * ASPLIT + t * PITCH);
        uint32_t* r1 = (uint32_t*)(smem + SM_A + 1 * ASPLIT + t * PITCH);
#pragma unroll
        for (int d = 0; d < DDIM; d += 2) {
            float va = -2.0f * xp[(size_t)d * HWSZ];
            float vb = -2.0f * xp[(size_t)(d + 1) * HWSZ];
            __nv_bfloat16 a0 = __float2bfloat16_rn(va);
            __nv_bfloat16 a1 = __float2bfloat16_rn(va - __bfloat162float(a0));
            __nv_bfloat16 b0 = __float2bfloat16_rn(vb);
            __nv_bfloat16 b1 = __float2bfloat16_rn(vb - __bfloat162float(b0));
            r0[d >> 1] = (uint32_t)__bfloat16_as_ushort(a0) |
                         ((uint32_t)__bfloat16_as_ushort(b0) << 16);
            r1[d >> 1] = (uint32_t)__bfloat16_as_ushort(a1) |
                         ((uint32_t)__bfloat16_as_ushort(b1) << 16);
        }
    }
    __syncthreads();

    // ---- A fragments resident in registers ----
    uint32_t af[2][4][4];
#pragma unroll
    for (int s = 0; s < 2; s++)
#pragma unroll
        for (int k = 0; k < 4; k++) {
            uint32_t addr = sbase + SM_A + s * ASPLIT +
                            (m0 + (lane & 15)) * PITCH + k * 32 + (lane >> 4) * 16;
            LDSM_X4(af[s][k], addr);
        }

    float bd0 = FLT_MAX, sd0 = FLT_MAX, bd1 = FLT_MAX, sd1 = FLT_MAX;
    int   bi0 = 0, bi1 = 0;

    for (int tt = 0; tt < 8; tt++) {
        if (tt < 7) { CP_WAIT1(); } else { CP_WAIT0(); }
        __syncthreads();
        const uint32_t bbase = sbase + SM_B + (tt & 1) * BBUF;

#pragma unroll 2
        for (int j = 0; j < 16; j++) {
            uint32_t bf[2][2][4];
#pragma unroll
            for (int s = 0; s < 2; s++)
#pragma unroll
                for (int kk = 0; kk < 2; kk++) {
                    uint32_t addr = bbase + s * BSPLIT +
                                    (j * 8 + (lane & 7)) * PITCH +
                                    kk * 64 + (lane >> 3) * 16;
                    LDSM_X4(bf[s][kk], addr);
                }

            // 3 independent accumulator chains for latency cover
            float accA[4] = {0.f, 0.f, 0.f, 0.f};
            float accB[4] = {0.f, 0.f, 0.f, 0.f};
            float accC[4] = {0.f, 0.f, 0.f, 0.f};
#pragma unroll
            for (int k = 0; k < 4; k++) {
                const uint32_t* b0k = &bf[0][k >> 1][(k & 1) * 2];
                const uint32_t* b1k = &bf[1][k >> 1][(k & 1) * 2];
                MMA16816(accA, af[0][k], b0k);   // x0*e0
                MMA16816(accB, af[0][k], b1k);   // x0*e1
                MMA16816(accC, af[1][k], b0k);   // x1*e0
            }

            const int cb = tt * 128 + j * 8 + 2 * tg;
            const float e0 = esq_s[cb], e1 = esq_s[cb + 1];
            upd2(bd0, bi0, sd0, e0 + ((accB[0] + accC[0]) + accA[0]), cb);
            upd2(bd0, bi0, sd0, e1 + ((accB[1] + accC[1]) + accA[1]), cb + 1);
            upd2(bd1, bi1, sd1, e0 + ((accB[2] + accC[2]) + accA[2]), cb);
            upd2(bd1, bi1, sd1, e1 + ((accB[3] + accC[3]) + accA[3]), cb + 1);
        }

        __syncthreads();
        if (tt + 2 < 8) issue_B(tt + 2, tt & 1);
    }

    // ---- merge top-2 across the 4 lanes sharing each row ----
#pragma unroll
    for (int off = 1; off <= 2; off <<= 1) {
        float obd = __shfl_xor_sync(0xffffffffu, bd0, off);
        int   obi = __shfl_xor_sync(0xffffffffu, bi0, off);
        float osd = __shfl_xor_sync(0xffffffffu, sd0, off);
        merge2(bd0, bi0, sd0, obd, obi, osd);
        obd = __shfl_xor_sync(0xffffffffu, bd1, off);
        obi = __shfl_xor_sync(0xffffffffu, bi1, off);
        osd = __shfl_xor_sync(0xffffffffu, sd1, off);
        merge2(bd1, bi1, sd1, obd, obi, osd);
    }
    if (tg == 0) {
        int g  = lane >> 2;
        int r0 = m0 + g, r1 = m0 + g + 8;
        fidx[r0] = bi0;
        fidx[r1] = bi1;
        if (sd0 - bd0 <= TAU) lst[atomicAdd(pcnt, 1)] = r0;
        if (sd1 - bd1 <= TAU) lst[atomicAdd(pcnt, 1)] = r1;
    }
    __syncthreads();

    // ---- near-tie rescan: one warp per flagged point, all 1024 codes,
    //      EXACT replica of Round-1 arithmetic ----
    {
        const int cnt = *pcnt;
        float* xv = (float*)(smem + SM_XV) + w * 64;
        for (int f = w; f < cnt; f += 8) {
            int r = lst[f];
            const float* xp = in + (size_t)b * DDIM * HWSZ +
                              ((base + r) & (HWSZ - 1));
            xv[lane]      = xp[(size_t)lane * HWSZ];
            xv[lane + 32] = xp[(size_t)(lane + 32) * HWSZ];
            __syncwarp();
            float bd = FLT_MAX; int bi = 0;
            for (int kc = 0; kc < 32; kc++) {
                int k = kc * 32 + lane;          // ascending in k per lane
                const float* ep = emb + (size_t)k * DDIM;
                float lo = 0.f, hi = 0.f;
#pragma unroll
                for (int d = 0; d < DDIM / 2; d++) {
                    lo = __fmaf_rn(xv[2 * d],     __ldg(&ep[2 * d]),     lo);
                    hi = __fmaf_rn(xv[2 * d + 1], __ldg(&ep[2 * d + 1]), hi);
                }
                float dot  = lo + hi;
                float dist = esq_s[k] - 2.0f * dot;
                if (dist < bd) { bd = dist; bi = k; }
            }
#pragma unroll
            for (int off = 16; off > 0; off >>= 1) {
                float od = __shfl_xor_sync(0xffffffffu, bd, off);
                int   oi = __shfl_xor_sync(0xffffffffu, bi, off);
                if (od < bd || (od == bd && oi < bi)) { bd = od; bi = oi; }
            }
            if (lane == 0) fidx[r] = bi;
            __syncwarp();
        }
    }
    __syncthreads();

    // ---- outputs ----
    if (t < 128) {
        int bidx = fidx[t];
        out[base + t] = (float)bidx;
        atomicAdd(&g_counts[bidx], 1);
    }
    {   // quantized scatter: 2 threads per point, 32 channels each
        int p    = t & 127;
        int half = t >> 7;
        int bidx = fidx[p];
        const float* er = emb + (size_t)bidx * DDIM + half * 32;
        float* oq = out + QOFF + (size_t)b * DDIM * HWSZ +
                    ((base + p) & (HWSZ - 1)) + (size_t)half * 32 * HWSZ;
#pragma unroll
        for (int i = 0; i < 32; i++)
            oq[(size_t)i * HWSZ] = __ldg(&er[i]);
    }
}

// ---------------------------------------------------------------------------
// Perplexity
// ---------------------------------------------------------------------------
__global__ void vq_perp(float* __restrict__ out) {
    __shared__ float red[32];
    int k = threadIdx.x;
    float p = (float)g_counts[k] * (1.0f / (float)NPTS);
    float v = p * logf(p + 1e-10f);
#pragma unroll
    for (int s = 16; s > 0; s >>= 1) v += __shfl_xor_sync(0xffffffffu, v, s);
    if ((k & 31) == 0) red[k >> 5] = v;
    __syncthreads();
    if (k < 32) {
        float wv = red[k];
#pragma unroll
        for (int s = 16; s > 0; s >>= 1) wv += __shfl_xor_sync(0xffffffffu, wv, s);
        if (k == 0) out[POFF] = expf(-wv);
    }
}

// ---------------------------------------------------------------------------
extern "C" void kernel_launch(void* const* d_in, const int* in_sizes, int n_in,
                              void* d_out, int out_size) {
    const float* x   = (const float*)d_in[0];   // (32, 64, 64, 64) fp32
    const float* emb = (const float*)d_in[1];   // (1024, 64) fp32
    float* out = (float*)d_out;

    cudaFuncSetAttribute(vq_main, cudaFuncAttributeMaxDynamicSharedMemorySize,
                         SM_TOTAL);

    vq_prep<<<8, 128>>>(emb);
    vq_split<<<8, 128>>>(emb);
    vq_main<<<NPTS / 128, 256, SM_TOTAL>>>(x, emb, out);
    vq_perp<<<1, KCODES>>>(out);
}

// round 9
// speedup vs baseline: 3.3657x; 1.2956x over previous
#include <cuda_runtime.h>
#include <cuda_bf16.h>
#include <math.h>
#include <float.h>
#include <stdint.h>

// Problem constants
#define NPTS   131072          // 32 * 64 * 64 points
#define DDIM   64
#define KCODES 1024
#define HWSZ   4096
#define QOFF   ((size_t)NPTS)
#define QSZ    ((size_t)32*64*4096)
#define POFF   (QOFF + QSZ)

#define TAU    2e-3f           // MMA top-2 gap below which we rescan exactly

#define PITCH   144            // bytes per smem row -> conflict-free ldmatrix
#define ASPLIT  (128 * PITCH)  // 18432 B per split tile
#define BUFSZ   (2 * ASPLIT)   // 36864 B: one B buffer (2 splits) == A region
// smem layout (A overlaid with B buffer 0!)
#define SM_ESQ   0             // 1024 f32 = 4096
#define SM_FIDX  4096          // 128 int final index
#define SM_CNT   4608          // flagged counter
#define SM_LST   4624          // 128 int flagged rows
#define SM_XV    5152          // 8 warps x 64 f32 rescan x-buffers (2048 B)
#define SM_BUF0  7200          // A splits during prologue, then B buf 0
#define SM_BUF1  (SM_BUF0 + BUFSZ)
#define SM_TOTAL (SM_BUF1 + BUFSZ)   // 80928 B -> 2 CTAs/SM

// ---- scratch (no cudaMalloc) ----
__device__ int           g_counts[KCODES];
__device__ float         g_esq[KCODES];
__device__ __nv_bfloat16 g_e0[KCODES * DDIM];
__device__ __nv_bfloat16 g_e1[KCODES * DDIM];

// ---- PTX helpers (baseline ISA, sm_80-compatible) ----
__device__ __forceinline__ uint32_t smem_u32(const void* p) {
    uint32_t a;
    asm("{ .reg .u64 t; cvta.to.shared.u64 t, %1; cvt.u32.u64 %0, t; }"
        : "=r"(a) : "l"(p));
    return a;
}
#define CP_ASYNC16(dst, src) \
    asm volatile("cp.async.cg.shared.global [%0], [%1], 16;" \
                 :: "r"(dst), "l"(src) : "memory")
#define CP_COMMIT() asm volatile("cp.async.commit_group;" ::: "memory")
#define CP_WAIT1()  asm volatile("cp.async.wait_group 1;" ::: "memory")
#define CP_WAIT0()  asm volatile("cp.async.wait_group 0;" ::: "memory")

#define LDSM_X4(r, addr)                                                      \
    asm volatile("ldmatrix.sync.aligned.m8n8.x4.shared.b16 {%0,%1,%2,%3}, [%4];" \
                 : "=r"((r)[0]), "=r"((r)[1]), "=r"((r)[2]), "=r"((r)[3])     \
                 : "r"(addr))

#define MMA16816(c, a, b)                                                     \
    asm volatile("mma.sync.aligned.m16n8k16.row.col.f32.bf16.bf16.f32 "       \
                 "{%0,%1,%2,%3}, {%4,%5,%6,%7}, {%8,%9}, {%0,%1,%2,%3};"      \
                 : "+f"((c)[0]), "+f"((c)[1]), "+f"((c)[2]), "+f"((c)[3])     \
                 : "r"((a)[0]), "r"((a)[1]), "r"((a)[2]), "r"((a)[3]),        \
                   "r"((b)[0]), "r"((b)[1]))

// best + second-best distance (index only for best)
__device__ __forceinline__ void upd2(float& bd, int& bi, float& sd,
                                     float d, int idx) {
    if (d < bd)      { sd = bd; bd = d; bi = idx; }
    else if (d < sd) { sd = d; }
}
__device__ __forceinline__ void merge2(float& bd, int& bi, float& sd,
                                       float obd, int obi, float osd) {
    if (obd < bd || (obd == bd && obi < bi)) {
        sd = fminf(bd, osd); bd = obd; bi = obi;
    } else {
        sd = fminf(sd, obd);
    }
}

// ---------------------------------------------------------------------------
// Prep: esq (VERBATIM Round-1 arithmetic — do not touch) + bf16 2-way splits.
// ---------------------------------------------------------------------------
__global__ void vq_prep(const float* __restrict__ emb) {
    int k = blockIdx.x * blockDim.x + threadIdx.x;
    if (k < KCODES) {
        const float4* row = (const float4*)(emb + (size_t)k * DDIM);
        float s = 0.f;
#pragma unroll
        for (int i = 0; i < DDIM / 4; i++) {
            float4 v = row[i];
            s += v.x * v.x + v.y * v.y + v.z * v.z + v.w * v.w;
        }
        g_esq[k]    = s;
        g_counts[k] = 0;
        const float* rowf = emb + (size_t)k * DDIM;
#pragma unroll 4
        for (int d = 0; d < DDIM; d++) {
            float v = rowf[d];
            __nv_bfloat16 h0 = __float2bfloat16_rn(v);
            __nv_bfloat16 h1 = __float2bfloat16_rn(v - __bfloat162float(h0));
            g_e0[(size_t)k * DDIM + d] = h0;
            g_e1[(size_t)k * DDIM + d] = h1;
        }
    }
}

// ---------------------------------------------------------------------------
// Main: 256 threads (8 warps), 128 points/CTA, 1024 CTAs, 2 CTAs/SM.
// 3-product bf16 mma.sync ranking + gap-gated exact R1-arithmetic rescan.
// A smem region is reused as B buffer 0 after fragments move to registers.
// ---------------------------------------------------------------------------
__global__ __launch_bounds__(256, 2)
void vq_main(const float* __restrict__ in, const float* __restrict__ emb,
             float* __restrict__ out) {
    extern __shared__ char smem[];
    float* esq_s = (float*)(smem + SM_ESQ);
    int*   fidx  = (int*)(smem + SM_FIDX);
    int*   pcnt  = (int*)(smem + SM_CNT);
    int*   lst   = (int*)(smem + SM_LST);
    const uint32_t sbase = smem_u32(smem);
    const int t    = threadIdx.x;
    const int lane = t & 31;
    const int w    = t >> 5;
    const int m0   = w * 16;
    const int base = blockIdx.x * 128;
    const int b    = base >> 12;
    const int tg   = lane & 3;

    // ---- B tile loader via cp.async: 2 splits x 128 codes x 128B ----
    auto issue_B = [&](int tt, int buf) {
        uint32_t bb = sbase + (buf ? SM_BUF1 : SM_BUF0);
#pragma unroll
        for (int i = 0; i < 8; i++) {
            int c   = t + i * 256;           // 0..2047 chunk id
            int s   = c >> 10;               // split 0/1
            int r   = c & 1023;
            int row = r >> 3, ch = r & 7;
            uint32_t dst = bb + s * ASPLIT + row * PITCH + ch * 16;
            const __nv_bfloat16* srcp = (s == 0) ? g_e0 : g_e1;
            const char* src = (const char*)srcp +
                              ((size_t)(tt * 128 + row) * DDIM + ch * 8) * 2;
            CP_ASYNC16(dst, src);
        }
        CP_COMMIT();
    };

    if (t == 0) *pcnt = 0;
#pragma unroll
    for (int i = 0; i < KCODES / 256; i++)
        esq_s[t + i * 256] = g_esq[t + i * 256];

    // ---- A build into BUF0: point t, split(-2x) into 2 bf16 rows ----
    if (t < 128) {
        const float* xp = in + (size_t)b * DDIM * HWSZ + ((base + t) & (HWSZ - 1));
        uint32_t* r0 = (uint32_t*)(smem + SM_BUF0 + 0 * ASPLIT + t * PITCH);
        uint32_t* r1 = (uint32_t*)(smem + SM_BUF0 + 1 * ASPLIT + t * PITCH);
#pragma unroll
        for (int d = 0; d < DDIM; d += 2) {
            float va = -2.0f * xp[(size_t)d * HWSZ];
            float vb = -2.0f * xp[(size_t)(d + 1) * HWSZ];
            __nv_bfloat16 a0 = __float2bfloat16_rn(va);
            __nv_bfloat16 a1 = __float2bfloat16_rn(va - __bfloat162float(a0));
            __nv_bfloat16 b0 = __float2bfloat16_rn(vb);
            __nv_bfloat16 b1 = __float2bfloat16_rn(vb - __bfloat162float(b0));
            r0[d >> 1] = (uint32_t)__bfloat16_as_ushort(a0) |
                         ((uint32_t)__bfloat16_as_ushort(b0) << 16);
            r1[d >> 1] = (uint32_t)__bfloat16_as_ushort(a1) |
                         ((uint32_t)__bfloat16_as_ushort(b1) << 16);
        }
    }
    __syncthreads();

    // ---- A fragments to registers (frees BUF0 for B tiles) ----
    uint32_t af[2][4][4];
#pragma unroll
    for (int s = 0; s < 2; s++)
#pragma unroll
        for (int k = 0; k < 4; k++) {
            uint32_t addr = sbase + SM_BUF0 + s * ASPLIT +
                            (m0 + (lane & 15)) * PITCH + k * 32 + (lane >> 4) * 16;
            LDSM_X4(af[s][k], addr);
        }
    __syncthreads();                         // all LDSM done before overwrite

    issue_B(0, 0);                           // into former A region
    issue_B(1, 1);

    float bd0 = FLT_MAX, sd0 = FLT_MAX, bd1 = FLT_MAX, sd1 = FLT_MAX;
    int   bi0 = 0, bi1 = 0;

    for (int tt = 0; tt < 8; tt++) {
        if (tt < 7) { CP_WAIT1(); } else { CP_WAIT0(); }
        __syncthreads();
        const uint32_t bbase = sbase + ((tt & 1) ? SM_BUF1 : SM_BUF0);

#pragma unroll 2
        for (int j = 0; j < 16; j++) {
            uint32_t bf[2][2][4];
#pragma unroll
            for (int s = 0; s < 2; s++)
#pragma unroll
                for (int kk = 0; kk < 2; kk++) {
                    uint32_t addr = bbase + s * ASPLIT +
                                    (j * 8 + (lane & 7)) * PITCH +
                                    kk * 64 + (lane >> 3) * 16;
                    LDSM_X4(bf[s][kk], addr);
                }

            float accA[4] = {0.f, 0.f, 0.f, 0.f};
            float accB[4] = {0.f, 0.f, 0.f, 0.f};
            float accC[4] = {0.f, 0.f, 0.f, 0.f};
#pragma unroll
            for (int k = 0; k < 4; k++) {
                const uint32_t* b0k = &bf[0][k >> 1][(k & 1) * 2];
                const uint32_t* b1k = &bf[1][k >> 1][(k & 1) * 2];
                MMA16816(accA, af[0][k], b0k);   // x0*e0
                MMA16816(accB, af[0][k], b1k);   // x0*e1
                MMA16816(accC, af[1][k], b0k);   // x1*e0
            }

            const int cb = tt * 128 + j * 8 + 2 * tg;
            const float e0 = esq_s[cb], e1 = esq_s[cb + 1];
            upd2(bd0, bi0, sd0, e0 + ((accB[0] + accC[0]) + accA[0]), cb);
            upd2(bd0, bi0, sd0, e1 + ((accB[1] + accC[1]) + accA[1]), cb + 1);
            upd2(bd1, bi1, sd1, e0 + ((accB[2] + accC[2]) + accA[2]), cb);
            upd2(bd1, bi1, sd1, e1 + ((accB[3] + accC[3]) + accA[3]), cb + 1);
        }

        __syncthreads();                     // everyone done reading buf
        if (tt + 2 < 8) issue_B(tt + 2, tt & 1);
    }

    // ---- merge top-2 across the 4 lanes sharing each row ----
#pragma unroll
    for (int off = 1; off <= 2; off <<= 1) {
        float obd = __shfl_xor_sync(0xffffffffu, bd0, off);
        int   obi = __shfl_xor_sync(0xffffffffu, bi0, off);
        float osd = __shfl_xor_sync(0xffffffffu, sd0, off);
        merge2(bd0, bi0, sd0, obd, obi, osd);
        obd = __shfl_xor_sync(0xffffffffu, bd1, off);
        obi = __shfl_xor_sync(0xffffffffu, bi1, off);
        osd = __shfl_xor_sync(0xffffffffu, sd1, off);
        merge2(bd1, bi1, sd1, obd, obi, osd);
    }
    if (tg == 0) {
        int g  = lane >> 2;
        int r0 = m0 + g, r1 = m0 + g + 8;
        fidx[r0] = bi0;
        fidx[r1] = bi1;
        if (sd0 - bd0 <= TAU) lst[atomicAdd(pcnt, 1)] = r0;
        if (sd1 - bd1 <= TAU) lst[atomicAdd(pcnt, 1)] = r1;
    }
    __syncthreads();

    // ---- near-tie rescan: one warp per flagged point, all 1024 codes,
    //      EXACT replica of Round-1 arithmetic ----
    {
        const int cnt = *pcnt;
        float* xv = (float*)(smem + SM_XV) + w * 64;
        for (int f = w; f < cnt; f += 8) {
            int r = lst[f];
            const float* xp = in + (size_t)b * DDIM * HWSZ +
                              ((base + r) & (HWSZ - 1));
            xv[lane]      = xp[(size_t)lane * HWSZ];
            xv[lane + 32] = xp[(size_t)(lane + 32) * HWSZ];
            __syncwarp();
            float bd = FLT_MAX; int bi = 0;
            for (int kc = 0; kc < 32; kc++) {
                int k = kc * 32 + lane;          // ascending in k per lane
                const float* ep = emb + (size_t)k * DDIM;
                float lo = 0.f, hi = 0.f;
#pragma unroll
                for (int d = 0; d < DDIM / 2; d++) {
                    lo = __fmaf_rn(xv[2 * d],     __ldg(&ep[2 * d]),     lo);
                    hi = __fmaf_rn(xv[2 * d + 1], __ldg(&ep[2 * d + 1]), hi);
                }
                float dot  = lo + hi;
                float dist = esq_s[k] - 2.0f * dot;
                if (dist < bd) { bd = dist; bi = k; }
            }
#pragma unroll
            for (int off = 16; off > 0; off >>= 1) {
                float od = __shfl_xor_sync(0xffffffffu, bd, off);
                int   oi = __shfl_xor_sync(0xffffffffu, bi, off);
                if (od < bd || (od == bd && oi < bi)) { bd = od; bi = oi; }
            }
            if (lane == 0) fidx[r] = bi;
            __syncwarp();
        }
    }
    __syncthreads();

    // ---- outputs ----
    if (t < 128) {
        int bidx = fidx[t];
        out[base + t] = (float)bidx;
        atomicAdd(&g_counts[bidx], 1);
    }
    {   // quantized scatter: 2 threads per point, 32 channels each
        int p    = t & 127;
        int half = t >> 7;
        int bidx = fidx[p];
        const float* er = emb + (size_t)bidx * DDIM + half * 32;
        float* oq = out + QOFF + (size_t)b * DDIM * HWSZ +
                    ((base + p) & (HWSZ - 1)) + (size_t)half * 32 * HWSZ;
#pragma unroll
        for (int i = 0; i < 32; i++)
            oq[(size_t)i * HWSZ] = __ldg(&er[i]);
    }
}

// ---------------------------------------------------------------------------
// Perplexity
// ---------------------------------------------------------------------------
__global__ void vq_perp(float* __restrict__ out) {
    __shared__ float red[32];
    int k = threadIdx.x;
    float p = (float)g_counts[k] * (1.0f / (float)NPTS);
    float v = p * logf(p + 1e-10f);
#pragma unroll
    for (int s = 16; s > 0; s >>= 1) v += __shfl_xor_sync(0xffffffffu, v, s);
    if ((k & 31) == 0) red[k >> 5] = v;
    __syncthreads();
    if (k < 32) {
        float wv = red[k];
#pragma unroll
        for (int s = 16; s > 0; s >>= 1) wv += __shfl_xor_sync(0xffffffffu, wv, s);
        if (k == 0) out[POFF] = expf(-wv);
    }
}

// ---------------------------------------------------------------------------
extern "C" void kernel_launch(void* const* d_in, const int* in_sizes, int n_in,
                              void* d_out, int out_size) {
    const float* x   = (const float*)d_in[0];   // (32, 64, 64, 64) fp32
    const float* emb = (const float*)d_in[1];   // (1024, 64) fp32
    float* out = (float*)d_out;

    cudaFuncSetAttribute(vq_main, cudaFuncAttributeMaxDynamicSharedMemorySize,
                         SM_TOTAL);

    vq_prep<<<8, 128>>>(emb);
    vq_main<<<NPTS / 128, 256, SM_TOTAL>>>(x, emb, out);
    vq_perp<<<1, KCODES>>>(out);
}